// round 2
// baseline (speedup 1.0000x reference)
#include <cuda_runtime.h>
#include <cstdint>

#define S_LEN 2048
#define DK 64
#define BH_N 32
#define SCALE 0.125f

// Row-wise 1/sum(exp) stats. Static device array (no allocations allowed).
__device__ float g_inv[BH_N * S_LEN];

// ---------------- packed f32x2 helpers (FFMA2: 2x fp32 FMA throughput) ----------------
__device__ __forceinline__ unsigned long long pack2(float x, float y) {
    unsigned long long r;
    asm("mov.b64 %0, {%1, %2};" : "=l"(r) : "f"(x), "f"(y));
    return r;
}
__device__ __forceinline__ void unpack2(unsigned long long v, float& x, float& y) {
    asm("mov.b64 {%0, %1}, %2;" : "=f"(x), "=f"(y) : "l"(v));
}
__device__ __forceinline__ unsigned long long ffma2(unsigned long long a,
                                                    unsigned long long b,
                                                    unsigned long long c) {
    unsigned long long d;
    asm("fma.rn.f32x2 %0, %1, %2, %3;" : "=l"(d) : "l"(a), "l"(b), "l"(c));
    return d;
}

// ---------------- XOR-swizzled transposed smem tile: element (d, row), row-width 128 ----
// Stored at d*128 + (((row>>2) ^ d) & 31)*4 + (row&3). Injective per d; keeps float4
// fragments (4 consecutive rows) contiguous + 16B aligned; spreads transpose-store banks.
__device__ __forceinline__ int swz(int d, int row) {
    return d * 128 + ((((row >> 2) ^ d) & 31) << 2) + (row & 3);
}
__device__ __forceinline__ int swz4(int d, int row4) {  // row4 multiple of 4
    return d * 128 + ((((row4 >> 2) ^ d) & 31) << 2);
}

// =======================================================================================
// K1: E[q,k] = mask ? 0 : exp( (Q.K^T) * 0.125 )     (unnormalized softmax numerator)
// 128x128 tile per block, 256 threads, 8x8 micro-tile, FFMA2 accumulators.
// Mask arrives as int32 (bool promoted by the harness): 0 = keep, nonzero = mask out.
// =======================================================================================
__global__ __launch_bounds__(256, 2)
void qk_exp_kernel(const float* __restrict__ Q, const float* __restrict__ K,
                   const int* __restrict__ M, float* __restrict__ E)
{
    extern __shared__ float sm[];
    float* Qs = sm;             // 64 x 128 swizzled, [d][q]
    float* Ks = sm + 64 * 128;  // 64 x 128 swizzled, [d][k]

    const int bh = blockIdx.z;
    const int q0 = blockIdx.y * 128;
    const int k0 = blockIdx.x * 128;
    const float* Qb = Q + (size_t)bh * S_LEN * DK;
    const float* Kb = K + (size_t)bh * S_LEN * DK;
    const int t = threadIdx.x;

    // Load 128x64 Q and K tiles, transposing into swizzled smem.
#pragma unroll
    for (int r = 0; r < 8; ++r) {
        const int row = (t >> 4) + r * 16;
        const int d0 = (t & 15) * 4;
        float4 v = *(const float4*)(Qb + (size_t)(q0 + row) * DK + d0);
        Qs[swz(d0 + 0, row)] = v.x; Qs[swz(d0 + 1, row)] = v.y;
        Qs[swz(d0 + 2, row)] = v.z; Qs[swz(d0 + 3, row)] = v.w;
        float4 w = *(const float4*)(Kb + (size_t)(k0 + row) * DK + d0);
        Ks[swz(d0 + 0, row)] = w.x; Ks[swz(d0 + 1, row)] = w.y;
        Ks[swz(d0 + 2, row)] = w.z; Ks[swz(d0 + 3, row)] = w.w;
    }
    __syncthreads();

    const int tx = t & 15, ty = t >> 4;
    unsigned long long acc[8][4];
#pragma unroll
    for (int i = 0; i < 8; ++i)
#pragma unroll
        for (int j = 0; j < 4; ++j) acc[i][j] = 0ULL;

#pragma unroll 8
    for (int d = 0; d < DK; ++d) {
        float4 a0 = *(const float4*)(Qs + swz4(d, ty * 8));
        float4 a1 = *(const float4*)(Qs + swz4(d, ty * 8 + 4));
        float4 b0 = *(const float4*)(Ks + swz4(d, tx * 8));
        float4 b1 = *(const float4*)(Ks + swz4(d, tx * 8 + 4));
        unsigned long long bp[4] = { pack2(b0.x, b0.y), pack2(b0.z, b0.w),
                                     pack2(b1.x, b1.y), pack2(b1.z, b1.w) };
        float av[8] = { a0.x, a0.y, a0.z, a0.w, a1.x, a1.y, a1.z, a1.w };
#pragma unroll
        for (int i = 0; i < 8; ++i) {
            unsigned long long ap = pack2(av[i], av[i]);
#pragma unroll
            for (int j = 0; j < 4; ++j)
                acc[i][j] = ffma2(ap, bp[j], acc[i][j]);
        }
    }

    float* Eb = E + (size_t)bh * S_LEN * S_LEN;
    const int* Mb = M + (size_t)bh * S_LEN * S_LEN;
#pragma unroll
    for (int i = 0; i < 8; ++i) {
        const int q = q0 + ty * 8 + i;
        const size_t off = (size_t)q * S_LEN + k0 + tx * 8;
        int4 m0 = *(const int4*)(Mb + off);
        int4 m1 = *(const int4*)(Mb + off + 4);
        float s[8];
#pragma unroll
        for (int j = 0; j < 4; ++j) unpack2(acc[i][j], s[2 * j], s[2 * j + 1]);
        float o[8];
        o[0] = m0.x ? 0.f : __expf(s[0] * SCALE);
        o[1] = m0.y ? 0.f : __expf(s[1] * SCALE);
        o[2] = m0.z ? 0.f : __expf(s[2] * SCALE);
        o[3] = m0.w ? 0.f : __expf(s[3] * SCALE);
        o[4] = m1.x ? 0.f : __expf(s[4] * SCALE);
        o[5] = m1.y ? 0.f : __expf(s[5] * SCALE);
        o[6] = m1.z ? 0.f : __expf(s[6] * SCALE);
        o[7] = m1.w ? 0.f : __expf(s[7] * SCALE);
        *(float4*)(Eb + off)     = make_float4(o[0], o[1], o[2], o[3]);
        *(float4*)(Eb + off + 4) = make_float4(o[4], o[5], o[6], o[7]);
    }
}

// =======================================================================================
// K2: row sums of E -> g_inv = 1/sum. One warp per row (max subtraction provably
// unnecessary: |logit| <= ~15, exp never overflows; masked entries are exactly 0).
// =======================================================================================
__global__ __launch_bounds__(256)
void rowsum_kernel(const float* __restrict__ E)
{
    const int row = blockIdx.x * 8 + (threadIdx.x >> 5);
    const int lane = threadIdx.x & 31;
    const float* p = E + (size_t)row * S_LEN;
    float s = 0.f;
#pragma unroll
    for (int i = 0; i < 16; ++i) {
        float4 v = *(const float4*)(p + i * 128 + lane * 4);
        s += (v.x + v.y) + (v.z + v.w);
    }
#pragma unroll
    for (int o = 16; o; o >>= 1) s += __shfl_xor_sync(0xffffffffu, s, o);
    if (lane == 0) g_inv[row] = 1.0f / s;
}

// =======================================================================================
// K3: in-place rewrite scores p = e * inv_row, and context = (E @ V) * inv_row.
// Block: 128 q-rows x full 64 d. k chunked by 128. 128 threads, 8x8 micro-tile, FFMA2.
// =======================================================================================
__global__ __launch_bounds__(128, 2)
void pv_kernel(const float* __restrict__ V, float* __restrict__ E, float* __restrict__ C)
{
    extern __shared__ float sm[];
    float* Es = sm;               // 128 x 128 swizzled, [k][q]
    float* Vs = sm + 128 * 128;   // 128 x 64, [k][d]

    const int bh = blockIdx.y;
    const int q0 = blockIdx.x * 128;
    const float* Vb = V + (size_t)bh * S_LEN * DK;
    float* Eb = E + ((size_t)bh * S_LEN + q0) * S_LEN;
    const float* invb = g_inv + (size_t)bh * S_LEN + q0;
    const int t = threadIdx.x;
    const int tx = t & 7, ty = t >> 3;

    unsigned long long acc[8][4];
#pragma unroll
    for (int i = 0; i < 8; ++i)
#pragma unroll
        for (int j = 0; j < 4; ++j) acc[i][j] = 0ULL;

    for (int kt = 0; kt < 16; ++kt) {
        const int k0 = kt * 128;
        // stage V chunk [128k x 64d]
#pragma unroll
        for (int r = 0; r < 16; ++r) {
            int f4 = t + r * 128;
            int k = f4 >> 4;
            int d = (f4 & 15) * 4;
            *(float4*)(Vs + k * DK + d) =
                *(const float4*)(Vb + (size_t)(k0 + k) * DK + d);
        }
        // stage E tile [128q x 128k] transposed+swizzled; rewrite p = e*inv in place
#pragma unroll
        for (int r = 0; r < 32; ++r) {
            int f4 = t + r * 128;
            int q = f4 >> 5;
            int kk = (f4 & 31) * 4;
            size_t goff = (size_t)q * S_LEN + k0 + kk;
            float4 e = *(const float4*)(Eb + goff);
            float inv = invb[q];
            *(float4*)(Eb + goff) = make_float4(e.x * inv, e.y * inv, e.z * inv, e.w * inv);
            Es[swz(kk + 0, q)] = e.x; Es[swz(kk + 1, q)] = e.y;
            Es[swz(kk + 2, q)] = e.z; Es[swz(kk + 3, q)] = e.w;
        }
        __syncthreads();

#pragma unroll 8
        for (int kk = 0; kk < 128; ++kk) {
            float4 a0 = *(const float4*)(Es + swz4(kk, ty * 8));
            float4 a1 = *(const float4*)(Es + swz4(kk, ty * 8 + 4));
            float4 b0 = *(const float4*)(Vs + kk * DK + tx * 8);
            float4 b1 = *(const float4*)(Vs + kk * DK + tx * 8 + 4);
            unsigned long long bp[4] = { pack2(b0.x, b0.y), pack2(b0.z, b0.w),
                                         pack2(b1.x, b1.y), pack2(b1.z, b1.w) };
            float av[8] = { a0.x, a0.y, a0.z, a0.w, a1.x, a1.y, a1.z, a1.w };
#pragma unroll
            for (int i = 0; i < 8; ++i) {
                unsigned long long ap = pack2(av[i], av[i]);
#pragma unroll
                for (int j = 0; j < 4; ++j)
                    acc[i][j] = ffma2(ap, bp[j], acc[i][j]);
            }
        }
        __syncthreads();
    }

    float* Cb = C + ((size_t)bh * S_LEN + q0) * DK;
#pragma unroll
    for (int i = 0; i < 8; ++i) {
        const int q = ty * 8 + i;
        const float inv = invb[q];
        float s[8];
#pragma unroll
        for (int j = 0; j < 4; ++j) unpack2(acc[i][j], s[2 * j], s[2 * j + 1]);
        *(float4*)(Cb + (size_t)q * DK + tx * 8) =
            make_float4(s[0] * inv, s[1] * inv, s[2] * inv, s[3] * inv);
        *(float4*)(Cb + (size_t)q * DK + tx * 8 + 4) =
            make_float4(s[4] * inv, s[5] * inv, s[6] * inv, s[7] * inv);
    }
}

// =======================================================================================
extern "C" void kernel_launch(void* const* d_in, const int* in_sizes, int n_in,
                              void* d_out, int out_size)
{
    const float* Q = (const float*)d_in[0];
    const float* K = (const float*)d_in[1];
    const float* V = (const float*)d_in[2];
    const int*   M = (const int*)d_in[3];

    float* ctx = (float*)d_out;                                 // [32, 2048, 64]
    float* E   = ctx + (size_t)BH_N * S_LEN * DK;               // [32, 2048, 2048]

    const int smem_k1 = 2 * 64 * 128 * (int)sizeof(float);            // 64 KB
    const int smem_k3 = (128 * 128 + 128 * 64) * (int)sizeof(float);  // 96 KB
    cudaFuncSetAttribute(qk_exp_kernel, cudaFuncAttributeMaxDynamicSharedMemorySize, smem_k1);
    cudaFuncSetAttribute(pv_kernel,     cudaFuncAttributeMaxDynamicSharedMemorySize, smem_k3);

    qk_exp_kernel<<<dim3(16, 16, BH_N), 256, smem_k1>>>(Q, K, M, E);
    rowsum_kernel<<<(BH_N * S_LEN) / 8, 256>>>(E);
    pv_kernel<<<dim3(16, BH_N), 128, smem_k3>>>(V, E, ctx);
}

// round 5
// speedup vs baseline: 1.5701x; 1.5701x over previous
#include <cuda_runtime.h>
#include <cuda_bf16.h>
#include <cstdint>

#define S_LEN 2048
#define DK 64
#define BH_N 32
#define SCALE 0.125f

// ---------------- static device scratch (no allocations allowed) ----------------
__device__ float g_inv[BH_N * S_LEN];                 // 1/rowsum
__device__ float g_part[BH_N * S_LEN * 16];           // per-ktile partial row sums
__device__ __nv_bfloat16 g_Qhi[BH_N * S_LEN * DK];
__device__ __nv_bfloat16 g_Qlo[BH_N * S_LEN * DK];
__device__ __nv_bfloat16 g_Khi[BH_N * S_LEN * DK];
__device__ __nv_bfloat16 g_Klo[BH_N * S_LEN * DK];
__device__ __nv_bfloat16 g_Vthi[BH_N * DK * S_LEN];   // [bh][d][s]
__device__ __nv_bfloat16 g_Vtlo[BH_N * DK * S_LEN];

// ---------------- helpers ----------------
__device__ __forceinline__ unsigned short bf_us(__nv_bfloat16 h) {
    return __bfloat16_as_ushort(h);
}
__device__ __forceinline__ void split2(float x, float y, uint32_t& hi, uint32_t& lo) {
    __nv_bfloat16 hx = __float2bfloat16(x), hy = __float2bfloat16(y);
    __nv_bfloat16 lx = __float2bfloat16(x - __bfloat162float(hx));
    __nv_bfloat16 ly = __float2bfloat16(y - __bfloat162float(hy));
    hi = (uint32_t)bf_us(hx) | ((uint32_t)bf_us(hy) << 16);
    lo = (uint32_t)bf_us(lx) | ((uint32_t)bf_us(ly) << 16);
}
__device__ __forceinline__ uint32_t ld32(const __nv_bfloat16* p) {
    return *(const uint32_t*)p;
}
// m16n8k16 row.col bf16 -> f32 accumulate (baseline PTX, sm_80+; fallback HMMA on sm_103)
__device__ __forceinline__ void mma_bf16(float* c, uint32_t a0, uint32_t a1,
                                         uint32_t a2, uint32_t a3,
                                         uint32_t b0, uint32_t b1) {
    asm volatile(
        "mma.sync.aligned.m16n8k16.row.col.f32.bf16.bf16.f32 "
        "{%0,%1,%2,%3}, {%4,%5,%6,%7}, {%8,%9}, {%0,%1,%2,%3};"
        : "+f"(c[0]), "+f"(c[1]), "+f"(c[2]), "+f"(c[3])
        : "r"(a0), "r"(a1), "r"(a2), "r"(a3), "r"(b0), "r"(b1));
}

#define PAD 72   // padded row stride (elements) -> fragment LDS bank = 4g+t (conflict-free)

// =======================================================================================
// K0a: Q,K fp32 -> bf16 hi/lo (same [bh][s][d] layout)
// =======================================================================================
__global__ __launch_bounds__(256)
void convert_qk(const float* __restrict__ Q, const float* __restrict__ K)
{
    const size_t i = ((size_t)blockIdx.x * 256 + threadIdx.x) * 4;
    const float* src = blockIdx.y ? K : Q;
    __nv_bfloat16* hi = blockIdx.y ? g_Khi : g_Qhi;
    __nv_bfloat16* lo = blockIdx.y ? g_Klo : g_Qlo;
    float4 v = *(const float4*)(src + i);
    uint2 h, l;
    split2(v.x, v.y, h.x, l.x);
    split2(v.z, v.w, h.y, l.y);
    *(uint2*)(hi + i) = h;
    *(uint2*)(lo + i) = l;
}

// =======================================================================================
// K0b: V [bh][s][d] fp32 -> transposed Vt [bh][d][s] bf16 hi/lo (64x64 tiles via smem)
// =======================================================================================
__global__ __launch_bounds__(256)
void convert_v(const float* __restrict__ V)
{
    __shared__ float sm[64 * 65];
    const int bh = blockIdx.y;
    const int k0 = blockIdx.x * 64;
    const float* Vb = V + ((size_t)bh * S_LEN + k0) * DK;
    const int t = threadIdx.x;
#pragma unroll
    for (int i = 0; i < 4; ++i) {
        int idx = i * 256 + t;
        int row = idx >> 4, c4 = (idx & 15) * 4;
        float4 v = *(const float4*)(Vb + (size_t)row * DK + c4);
        sm[row * 65 + c4 + 0] = v.x; sm[row * 65 + c4 + 1] = v.y;
        sm[row * 65 + c4 + 2] = v.z; sm[row * 65 + c4 + 3] = v.w;
    }
    __syncthreads();
    const int d = t >> 2, qtr = t & 3;
    __nv_bfloat16* ph = g_Vthi + ((size_t)bh * DK + d) * S_LEN + k0 + qtr * 16;
    __nv_bfloat16* pl = g_Vtlo + ((size_t)bh * DK + d) * S_LEN + k0 + qtr * 16;
    uint32_t hw[8], lw[8];
#pragma unroll
    for (int j = 0; j < 8; ++j) {
        float a = sm[(qtr * 16 + 2 * j + 0) * 65 + d];
        float b = sm[(qtr * 16 + 2 * j + 1) * 65 + d];
        split2(a, b, hw[j], lw[j]);
    }
    *(uint4*)(ph + 0) = make_uint4(hw[0], hw[1], hw[2], hw[3]);
    *(uint4*)(ph + 8) = make_uint4(hw[4], hw[5], hw[6], hw[7]);
    *(uint4*)(pl + 0) = make_uint4(lw[0], lw[1], lw[2], lw[3]);
    *(uint4*)(pl + 8) = make_uint4(lw[4], lw[5], lw[6], lw[7]);
}

// =======================================================================================
// K1: E = mask ? 0 : exp(QK^T/8) via mma.sync bf16 hi/lo. 128x128 tile, 8 warps.
// Warp tile 32(m) x 64(n). Fused per-row partial sums into g_part[row][kt].
// smem layout (bytes): Qhi@0, Qlo@18432, Khi@36864, Klo@55296 (each 128xPAD bf16),
//                      red@73728 (128 floats)
// =======================================================================================
__global__ __launch_bounds__(256)
void qk_mma(const int* __restrict__ M, float* __restrict__ E)
{
    extern __shared__ char smem[];
    __nv_bfloat16* Qh = (__nv_bfloat16*)(smem);
    __nv_bfloat16* Ql = (__nv_bfloat16*)(smem + 18432);
    __nv_bfloat16* Kh = (__nv_bfloat16*)(smem + 36864);
    __nv_bfloat16* Kl = (__nv_bfloat16*)(smem + 55296);
    float* red = (float*)(smem + 73728);

    const int t = threadIdx.x, wid = t >> 5, lane = t & 31;
    const int g = lane >> 2, tq = lane & 3;
    const int bh = blockIdx.z, q0 = blockIdx.y * 128, k0 = blockIdx.x * 128;
    const int kt = blockIdx.x;
    const int m0 = (wid >> 1) * 32;       // warp rows
    const int n0 = (wid & 1) * 64;        // warp cols

    if (t < 128) red[t] = 0.f;

    // stage 4 tiles: 128 rows x 64 bf16, padded stride PAD
    {
        const __nv_bfloat16* srcs[4] = {
            g_Qhi + ((size_t)bh * S_LEN + q0) * DK, g_Qlo + ((size_t)bh * S_LEN + q0) * DK,
            g_Khi + ((size_t)bh * S_LEN + k0) * DK, g_Klo + ((size_t)bh * S_LEN + k0) * DK };
        __nv_bfloat16* dsts[4] = { Qh, Ql, Kh, Kl };
#pragma unroll
        for (int ts = 0; ts < 4; ++ts) {
#pragma unroll
            for (int p = 0; p < 4; ++p) {
                int idx = p * 256 + t;
                int r = idx >> 3, c8 = (idx & 7) * 8;
                *(uint4*)(dsts[ts] + r * PAD + c8) = *(const uint4*)(srcs[ts] + r * DK + c8);
            }
        }
    }
    __syncthreads();

    float c[2][8][4];
#pragma unroll
    for (int mt = 0; mt < 2; ++mt)
#pragma unroll
        for (int nt = 0; nt < 8; ++nt)
#pragma unroll
            for (int j = 0; j < 4; ++j) c[mt][nt][j] = 0.f;

    const __nv_bfloat16* Ap[3] = { Qh, Qh, Ql };
    const __nv_bfloat16* Bp[3] = { Kh, Kl, Kh };
#pragma unroll
    for (int p = 0; p < 3; ++p) {
#pragma unroll
        for (int ks = 0; ks < 4; ++ks) {
            uint32_t a[2][4];
#pragma unroll
            for (int mt = 0; mt < 2; ++mt) {
                const __nv_bfloat16* ap = Ap[p] + (m0 + mt * 16 + g) * PAD + ks * 16;
                a[mt][0] = ld32(ap + 2 * tq);
                a[mt][1] = ld32(ap + 8 * PAD + 2 * tq);
                a[mt][2] = ld32(ap + 2 * tq + 8);
                a[mt][3] = ld32(ap + 8 * PAD + 2 * tq + 8);
            }
#pragma unroll
            for (int nt = 0; nt < 8; ++nt) {
                const __nv_bfloat16* bp = Bp[p] + (n0 + nt * 8 + g) * PAD + ks * 16;
                uint32_t b0 = ld32(bp + 2 * tq);
                uint32_t b1 = ld32(bp + 2 * tq + 8);
#pragma unroll
                for (int mt = 0; mt < 2; ++mt)
                    mma_bf16(c[mt][nt], a[mt][0], a[mt][1], a[mt][2], a[mt][3], b0, b1);
            }
        }
    }

    // epilogue: exp + mask + store + partial row sums
    float* Eb = E + (((size_t)bh * S_LEN + q0) * S_LEN) + k0;
    const int* Mb = M + (((size_t)bh * S_LEN + q0) * S_LEN) + k0;
#pragma unroll
    for (int mt = 0; mt < 2; ++mt) {
#pragma unroll
        for (int h = 0; h < 2; ++h) {
            const int rloc = m0 + mt * 16 + g + h * 8;
            float s = 0.f;
#pragma unroll
            for (int nt = 0; nt < 8; ++nt) {
                const int col = n0 + nt * 8 + 2 * tq;
                const size_t off = (size_t)rloc * S_LEN + col;
                int2 m = *(const int2*)(Mb + off);
                float e0 = m.x ? 0.f : __expf(c[mt][nt][h * 2 + 0] * SCALE);
                float e1 = m.y ? 0.f : __expf(c[mt][nt][h * 2 + 1] * SCALE);
                *(float2*)(Eb + off) = make_float2(e0, e1);
                s += e0 + e1;
            }
            s += __shfl_xor_sync(0xffffffffu, s, 1);
            s += __shfl_xor_sync(0xffffffffu, s, 2);
            if (tq == 0) atomicAdd(&red[rloc], s);
        }
    }
    __syncthreads();
    if (t < 128)
        g_part[((size_t)bh * S_LEN + q0 + t) * 16 + kt] = red[t];
}

// =======================================================================================
// K2: g_inv = 1 / sum of 16 partials per row
// =======================================================================================
__global__ __launch_bounds__(256)
void rowsum2()
{
    const int r = blockIdx.x * 256 + threadIdx.x;
    const float4* p = (const float4*)(g_part + (size_t)r * 16);
    float4 a = p[0], b = p[1], c = p[2], d = p[3];
    float s = ((a.x + a.y) + (a.z + a.w)) + ((b.x + b.y) + (b.z + b.w)) +
              ((c.x + c.y) + (c.z + c.w)) + ((d.x + d.y) + (d.z + d.w));
    g_inv[r] = 1.0f / s;
}

// =======================================================================================
// K3: scores p = e*inv written in-place; context = P @ V via mma.sync bf16 hi/lo.
// Block: 128 q x 64 d, 8 warps, warp tile 32(m) x 32(n). k chunks of 64, 32 chunks.
// smem: Eh@0, El@18432 (128xPAD), Vh@36864, Vl@46080 (64xPAD). Total 55296B.
// Normalization folded into staged operand; epilogue is a plain store.
// =======================================================================================
__global__ __launch_bounds__(256)
void pv_mma(float* __restrict__ E, float* __restrict__ C)
{
    extern __shared__ char smem[];
    __nv_bfloat16* Eh = (__nv_bfloat16*)(smem);
    __nv_bfloat16* El = (__nv_bfloat16*)(smem + 18432);
    __nv_bfloat16* Vh = (__nv_bfloat16*)(smem + 36864);
    __nv_bfloat16* Vl = (__nv_bfloat16*)(smem + 46080);

    const int t = threadIdx.x, wid = t >> 5, lane = t & 31;
    const int g = lane >> 2, tq = lane & 3;
    const int bh = blockIdx.y, q0 = blockIdx.x * 128;
    const int m0 = (wid >> 1) * 32;
    const int n0 = (wid & 1) * 32;

    float* Eb = E + ((size_t)bh * S_LEN + q0) * S_LEN;
    const float* invp = g_inv + (size_t)bh * S_LEN + q0;
    const __nv_bfloat16* vh = g_Vthi + (size_t)bh * DK * S_LEN;
    const __nv_bfloat16* vl = g_Vtlo + (size_t)bh * DK * S_LEN;

    float c[2][4][4];
#pragma unroll
    for (int mt = 0; mt < 2; ++mt)
#pragma unroll
        for (int nt = 0; nt < 4; ++nt)
#pragma unroll
            for (int j = 0; j < 4; ++j) c[mt][nt][j] = 0.f;

    for (int kc = 0; kc < 32; ++kc) {
        const int k0 = kc * 64;
        // stage E chunk: read, normalize, write back, split into smem (normalized)
#pragma unroll
        for (int it = 0; it < 8; ++it) {
            int idx = it * 256 + t;
            int row = idx >> 4, c4 = (idx & 15) * 4;
            const size_t go = (size_t)row * S_LEN + k0 + c4;
            float4 e = *(const float4*)(Eb + go);
            const float inv = invp[row];
            e.x *= inv; e.y *= inv; e.z *= inv; e.w *= inv;
            *(float4*)(Eb + go) = e;
            uint32_t h0, l0, h1, l1;
            split2(e.x, e.y, h0, l0);
            split2(e.z, e.w, h1, l1);
            *(uint2*)(Eh + row * PAD + c4) = make_uint2(h0, h1);
            *(uint2*)(El + row * PAD + c4) = make_uint2(l0, l1);
        }
        // stage Vt chunk: 64 d-rows x 64 k
#pragma unroll
        for (int it = 0; it < 2; ++it) {
            int idx = it * 256 + t;
            int d = idx >> 3, c8 = (idx & 7) * 8;
            const size_t go = (size_t)d * S_LEN + k0 + c8;
            *(uint4*)(Vh + d * PAD + c8) = *(const uint4*)(vh + go);
            *(uint4*)(Vl + d * PAD + c8) = *(const uint4*)(vl + go);
        }
        __syncthreads();

        const __nv_bfloat16* Ap[3] = { Eh, Eh, El };
        const __nv_bfloat16* Bp[3] = { Vh, Vl, Vh };
#pragma unroll
        for (int p = 0; p < 3; ++p) {
#pragma unroll
            for (int ks = 0; ks < 4; ++ks) {
                uint32_t a[2][4];
#pragma unroll
                for (int mt = 0; mt < 2; ++mt) {
                    const __nv_bfloat16* ap = Ap[p] + (m0 + mt * 16 + g) * PAD + ks * 16;
                    a[mt][0] = ld32(ap + 2 * tq);
                    a[mt][1] = ld32(ap + 8 * PAD + 2 * tq);
                    a[mt][2] = ld32(ap + 2 * tq + 8);
                    a[mt][3] = ld32(ap + 8 * PAD + 2 * tq + 8);
                }
#pragma unroll
                for (int nt = 0; nt < 4; ++nt) {
                    const __nv_bfloat16* bp = Bp[p] + (n0 + nt * 8 + g) * PAD + ks * 16;
                    uint32_t b0 = ld32(bp + 2 * tq);
                    uint32_t b1 = ld32(bp + 2 * tq + 8);
#pragma unroll
                    for (int mt = 0; mt < 2; ++mt)
                        mma_bf16(c[mt][nt], a[mt][0], a[mt][1], a[mt][2], a[mt][3], b0, b1);
                }
            }
        }
        __syncthreads();
    }

    float* Cb = C + ((size_t)bh * S_LEN + q0) * DK;
#pragma unroll
    for (int mt = 0; mt < 2; ++mt)
#pragma unroll
        for (int h = 0; h < 2; ++h) {
            const int q = m0 + mt * 16 + g + h * 8;
#pragma unroll
            for (int nt = 0; nt < 4; ++nt) {
                const int d = n0 + nt * 8 + 2 * tq;
                *(float2*)(Cb + (size_t)q * DK + d) =
                    make_float2(c[mt][nt][h * 2 + 0], c[mt][nt][h * 2 + 1]);
            }
        }
}

// =======================================================================================
extern "C" void kernel_launch(void* const* d_in, const int* in_sizes, int n_in,
                              void* d_out, int out_size)
{
    const float* Q = (const float*)d_in[0];
    const float* K = (const float*)d_in[1];
    const float* V = (const float*)d_in[2];
    const int*   M = (const int*)d_in[3];

    float* ctx = (float*)d_out;
    float* E   = ctx + (size_t)BH_N * S_LEN * DK;

    const int smem_k1 = 73728 + 512;   // 4 tiles + red
    const int smem_k3 = 55296;
    cudaFuncSetAttribute(qk_mma, cudaFuncAttributeMaxDynamicSharedMemorySize, smem_k1);
    cudaFuncSetAttribute(pv_mma, cudaFuncAttributeMaxDynamicSharedMemorySize, smem_k3);

    convert_qk<<<dim3(4096, 2), 256>>>(Q, K);
    convert_v<<<dim3(32, BH_N), 256>>>(V);
    qk_mma<<<dim3(16, 16, BH_N), 256, smem_k1>>>(M, E);
    rowsum2<<<(BH_N * S_LEN) / 256, 256>>>();
    pv_mma<<<dim3(16, BH_N), 256, smem_k3>>>(E, ctx);
}

// round 6
// speedup vs baseline: 1.6222x; 1.0332x over previous
#include <cuda_runtime.h>
#include <cuda_bf16.h>
#include <cstdint>

#define S_LEN 2048
#define DK 64
#define BH_N 32
#define SCALE 0.125f
#define PAD 72   // padded smem row stride (elems): fragment LDS conflict-free

// ---------------- static device scratch (no allocations allowed) ----------------
__device__ float g_inv[BH_N * S_LEN];
__device__ __nv_bfloat16 g_Qhi[BH_N * S_LEN * DK];
__device__ __nv_bfloat16 g_Qlo[BH_N * S_LEN * DK];
__device__ __nv_bfloat16 g_Khi[BH_N * S_LEN * DK];
__device__ __nv_bfloat16 g_Klo[BH_N * S_LEN * DK];
__device__ __nv_bfloat16 g_Vthi[BH_N * DK * S_LEN];   // [bh][d][s]
__device__ __nv_bfloat16 g_Vtlo[BH_N * DK * S_LEN];

// ---------------- helpers ----------------
__device__ __forceinline__ unsigned short bf_us(__nv_bfloat16 h) {
    return __bfloat16_as_ushort(h);
}
__device__ __forceinline__ void split2(float x, float y, uint32_t& hi, uint32_t& lo) {
    __nv_bfloat16 hx = __float2bfloat16(x), hy = __float2bfloat16(y);
    __nv_bfloat16 lx = __float2bfloat16(x - __bfloat162float(hx));
    __nv_bfloat16 ly = __float2bfloat16(y - __bfloat162float(hy));
    hi = (uint32_t)bf_us(hx) | ((uint32_t)bf_us(hy) << 16);
    lo = (uint32_t)bf_us(lx) | ((uint32_t)bf_us(ly) << 16);
}
__device__ __forceinline__ uint32_t ld32(const __nv_bfloat16* p) {
    return *(const uint32_t*)p;
}
__device__ __forceinline__ void mma_bf16(float* c, uint32_t a0, uint32_t a1,
                                         uint32_t a2, uint32_t a3,
                                         uint32_t b0, uint32_t b1) {
    asm volatile(
        "mma.sync.aligned.m16n8k16.row.col.f32.bf16.bf16.f32 "
        "{%0,%1,%2,%3}, {%4,%5,%6,%7}, {%8,%9}, {%0,%1,%2,%3};"
        : "+f"(c[0]), "+f"(c[1]), "+f"(c[2]), "+f"(c[3])
        : "r"(a0), "r"(a1), "r"(a2), "r"(a3), "r"(b0), "r"(b1));
}

// =======================================================================================
// K0a: Q,K fp32 -> bf16 hi/lo
// =======================================================================================
__global__ __launch_bounds__(256)
void convert_qk(const float* __restrict__ Q, const float* __restrict__ K)
{
    const size_t i = ((size_t)blockIdx.x * 256 + threadIdx.x) * 4;
    const float* src = blockIdx.y ? K : Q;
    __nv_bfloat16* hi = blockIdx.y ? g_Khi : g_Qhi;
    __nv_bfloat16* lo = blockIdx.y ? g_Klo : g_Qlo;
    float4 v = *(const float4*)(src + i);
    uint2 h, l;
    split2(v.x, v.y, h.x, l.x);
    split2(v.z, v.w, h.y, l.y);
    *(uint2*)(hi + i) = h;
    *(uint2*)(lo + i) = l;
}

// =======================================================================================
// K0b: V [bh][s][d] fp32 -> transposed Vt [bh][d][s] bf16 hi/lo
// =======================================================================================
__global__ __launch_bounds__(256)
void convert_v(const float* __restrict__ V)
{
    __shared__ float sm[64 * 65];
    const int bh = blockIdx.y;
    const int k0 = blockIdx.x * 64;
    const float* Vb = V + ((size_t)bh * S_LEN + k0) * DK;
    const int t = threadIdx.x;
#pragma unroll
    for (int i = 0; i < 4; ++i) {
        int idx = i * 256 + t;
        int row = idx >> 4, c4 = (idx & 15) * 4;
        float4 v = *(const float4*)(Vb + (size_t)row * DK + c4);
        sm[row * 65 + c4 + 0] = v.x; sm[row * 65 + c4 + 1] = v.y;
        sm[row * 65 + c4 + 2] = v.z; sm[row * 65 + c4 + 3] = v.w;
    }
    __syncthreads();
    const int d = t >> 2, qtr = t & 3;
    __nv_bfloat16* ph = g_Vthi + ((size_t)bh * DK + d) * S_LEN + k0 + qtr * 16;
    __nv_bfloat16* pl = g_Vtlo + ((size_t)bh * DK + d) * S_LEN + k0 + qtr * 16;
    uint32_t hw[8], lw[8];
#pragma unroll
    for (int j = 0; j < 8; ++j) {
        float a = sm[(qtr * 16 + 2 * j + 0) * 65 + d];
        float b = sm[(qtr * 16 + 2 * j + 1) * 65 + d];
        split2(a, b, hw[j], lw[j]);
    }
    *(uint4*)(ph + 0) = make_uint4(hw[0], hw[1], hw[2], hw[3]);
    *(uint4*)(ph + 8) = make_uint4(hw[4], hw[5], hw[6], hw[7]);
    *(uint4*)(pl + 0) = make_uint4(lw[0], lw[1], lw[2], lw[3]);
    *(uint4*)(pl + 8) = make_uint4(lw[4], lw[5], lw[6], lw[7]);
}

// =======================================================================================
// Fused attention: per 128-q block, loop 32 k-chunks of 64:
//   QK mma (hi/lo) -> exp+mask -> E store (unnormalized) + reg row-sums
//   -> P packed to bf16 hi/lo IN REGISTERS -> PV mma. Epilogue: g_inv + context.
// 8 warps, warp tile 16(m) x 64(n). Double-buffered K/V chunk staging.
// smem (bytes): Qh@0 Ql@18432 (128xPAD), Kh2@36864, Kl2@55296, Vh2@73728, Vl2@92160
//   (each 2 bufs x 64xPAD x 2B = 2x9216). Total 110592.
// =======================================================================================
__global__ __launch_bounds__(256)
void attn_fused(const int* __restrict__ M, float* __restrict__ E, float* __restrict__ C)
{
    extern __shared__ char smem[];
    __nv_bfloat16* Qh = (__nv_bfloat16*)(smem);
    __nv_bfloat16* Ql = (__nv_bfloat16*)(smem + 18432);
    __nv_bfloat16* Kh[2] = { (__nv_bfloat16*)(smem + 36864), (__nv_bfloat16*)(smem + 46080) };
    __nv_bfloat16* Kl[2] = { (__nv_bfloat16*)(smem + 55296), (__nv_bfloat16*)(smem + 64512) };
    __nv_bfloat16* Vh[2] = { (__nv_bfloat16*)(smem + 73728), (__nv_bfloat16*)(smem + 82944) };
    __nv_bfloat16* Vl[2] = { (__nv_bfloat16*)(smem + 92160), (__nv_bfloat16*)(smem + 101376) };

    const int t = threadIdx.x, wid = t >> 5, lane = t & 31;
    const int g = lane >> 2, tq = lane & 3;
    const int bh = blockIdx.y, q0 = blockIdx.x * 128;
    const int m0 = wid * 16;

    const __nv_bfloat16* Kp_h = g_Khi + ((size_t)bh * S_LEN) * DK;
    const __nv_bfloat16* Kp_l = g_Klo + ((size_t)bh * S_LEN) * DK;
    const __nv_bfloat16* Vp_h = g_Vthi + (size_t)bh * DK * S_LEN;
    const __nv_bfloat16* Vp_l = g_Vtlo + (size_t)bh * DK * S_LEN;

    // stage Q once (128 x 64, hi/lo)
    {
        const __nv_bfloat16* qh = g_Qhi + ((size_t)bh * S_LEN + q0) * DK;
        const __nv_bfloat16* ql = g_Qlo + ((size_t)bh * S_LEN + q0) * DK;
#pragma unroll
        for (int i = 0; i < 4; ++i) {
            int idx = i * 256 + t;
            int r = idx >> 3, c8 = (idx & 7) * 8;
            *(uint4*)(Qh + r * PAD + c8) = *(const uint4*)(qh + r * DK + c8);
            *(uint4*)(Ql + r * PAD + c8) = *(const uint4*)(ql + r * DK + c8);
        }
    }

    // row/col indices for chunk staging: thread covers idx, idx+256
    const int sr0 = t >> 3, sc0 = (t & 7) * 8;
    const int sr1 = (t + 256) >> 3, sc1 = ((t + 256) & 7) * 8;

    // stage chunk 0 into buffer 0
    {
        const int k0 = 0;
        *(uint4*)(Kh[0] + sr0 * PAD + sc0) = *(const uint4*)(Kp_h + (size_t)(k0 + sr0) * DK + sc0);
        *(uint4*)(Kh[0] + sr1 * PAD + sc1) = *(const uint4*)(Kp_h + (size_t)(k0 + sr1) * DK + sc1);
        *(uint4*)(Kl[0] + sr0 * PAD + sc0) = *(const uint4*)(Kp_l + (size_t)(k0 + sr0) * DK + sc0);
        *(uint4*)(Kl[0] + sr1 * PAD + sc1) = *(const uint4*)(Kp_l + (size_t)(k0 + sr1) * DK + sc1);
        *(uint4*)(Vh[0] + sr0 * PAD + sc0) = *(const uint4*)(Vp_h + (size_t)sr0 * S_LEN + k0 + sc0);
        *(uint4*)(Vh[0] + sr1 * PAD + sc1) = *(const uint4*)(Vp_h + (size_t)sr1 * S_LEN + k0 + sc1);
        *(uint4*)(Vl[0] + sr0 * PAD + sc0) = *(const uint4*)(Vp_l + (size_t)sr0 * S_LEN + k0 + sc0);
        *(uint4*)(Vl[0] + sr1 * PAD + sc1) = *(const uint4*)(Vp_l + (size_t)sr1 * S_LEN + k0 + sc1);
    }

    float d[8][4];   // PV accumulators (rows g,g+8 x d-cols)
#pragma unroll
    for (int nt = 0; nt < 8; ++nt)
#pragma unroll
        for (int j = 0; j < 4; ++j) d[nt][j] = 0.f;
    float rs0 = 0.f, rs1 = 0.f;

    float* Eb = E + ((size_t)bh * S_LEN + q0) * S_LEN;
    const int* Mb = M + ((size_t)bh * S_LEN + q0) * S_LEN;

    for (int kc = 0; kc < 32; ++kc) {
        const int cur = kc & 1;
        __syncthreads();   // stage(cur) visible; all warps done with buffer cur^1

        // prefetch next chunk (LDG now, STS at end of iteration)
        uint4 pf[8];
        if (kc + 1 < 32) {
            const int kn = (kc + 1) * 64;
            pf[0] = *(const uint4*)(Kp_h + (size_t)(kn + sr0) * DK + sc0);
            pf[1] = *(const uint4*)(Kp_h + (size_t)(kn + sr1) * DK + sc1);
            pf[2] = *(const uint4*)(Kp_l + (size_t)(kn + sr0) * DK + sc0);
            pf[3] = *(const uint4*)(Kp_l + (size_t)(kn + sr1) * DK + sc1);
            pf[4] = *(const uint4*)(Vp_h + (size_t)sr0 * S_LEN + kn + sc0);
            pf[5] = *(const uint4*)(Vp_h + (size_t)sr1 * S_LEN + kn + sc1);
            pf[6] = *(const uint4*)(Vp_l + (size_t)sr0 * S_LEN + kn + sc0);
            pf[7] = *(const uint4*)(Vp_l + (size_t)sr1 * S_LEN + kn + sc1);
        }

        // prefetch mask for this chunk (consumed in epilogue; covered by QK mma)
        int2 mk[16];
#pragma unroll
        for (int h = 0; h < 2; ++h)
#pragma unroll
            for (int nt = 0; nt < 8; ++nt)
                mk[h * 8 + nt] = *(const int2*)(Mb + (size_t)(m0 + g + h * 8) * S_LEN
                                                + kc * 64 + nt * 8 + 2 * tq);

        // ---- QK mma ----
        float c[8][4];
#pragma unroll
        for (int nt = 0; nt < 8; ++nt)
#pragma unroll
            for (int j = 0; j < 4; ++j) c[nt][j] = 0.f;

#pragma unroll
        for (int ks = 0; ks < 4; ++ks) {
            const __nv_bfloat16* aph = Qh + (m0 + g) * PAD + ks * 16;
            const __nv_bfloat16* apl = Ql + (m0 + g) * PAD + ks * 16;
            uint32_t aH[4] = { ld32(aph + 2 * tq), ld32(aph + 8 * PAD + 2 * tq),
                               ld32(aph + 2 * tq + 8), ld32(aph + 8 * PAD + 2 * tq + 8) };
            uint32_t aL[4] = { ld32(apl + 2 * tq), ld32(apl + 8 * PAD + 2 * tq),
                               ld32(apl + 2 * tq + 8), ld32(apl + 8 * PAD + 2 * tq + 8) };
#pragma unroll
            for (int nt = 0; nt < 8; ++nt) {
                const __nv_bfloat16* bph = Kh[cur] + (nt * 8 + g) * PAD + ks * 16;
                const __nv_bfloat16* bpl = Kl[cur] + (nt * 8 + g) * PAD + ks * 16;
                uint32_t bH0 = ld32(bph + 2 * tq), bH1 = ld32(bph + 2 * tq + 8);
                uint32_t bL0 = ld32(bpl + 2 * tq), bL1 = ld32(bpl + 2 * tq + 8);
                mma_bf16(c[nt], aH[0], aH[1], aH[2], aH[3], bH0, bH1);
                mma_bf16(c[nt], aH[0], aH[1], aH[2], aH[3], bL0, bL1);
                mma_bf16(c[nt], aL[0], aL[1], aL[2], aL[3], bH0, bH1);
            }
        }

        // ---- epilogue: exp + mask + E store + row sums + pack P (registers) ----
        uint32_t ph0[8], ph1[8], pl0[8], pl1[8];
#pragma unroll
        for (int nt = 0; nt < 8; ++nt) {
            int2 ma = mk[nt], mb = mk[8 + nt];
            float e0 = ma.x ? 0.f : __expf(c[nt][0] * SCALE);
            float e1 = ma.y ? 0.f : __expf(c[nt][1] * SCALE);
            float e2 = mb.x ? 0.f : __expf(c[nt][2] * SCALE);
            float e3 = mb.y ? 0.f : __expf(c[nt][3] * SCALE);
            const size_t col = (size_t)kc * 64 + nt * 8 + 2 * tq;
            *(float2*)(Eb + (size_t)(m0 + g) * S_LEN + col)     = make_float2(e0, e1);
            *(float2*)(Eb + (size_t)(m0 + g + 8) * S_LEN + col) = make_float2(e2, e3);
            rs0 += e0 + e1;
            rs1 += e2 + e3;
            split2(e0, e1, ph0[nt], pl0[nt]);
            split2(e2, e3, ph1[nt], pl1[nt]);
        }

        // ---- PV mma: A = packed P fragments (regs), B = Vt chunk (smem) ----
#pragma unroll
        for (int ks = 0; ks < 4; ++ks) {
            uint32_t aH0 = ph0[2 * ks], aH1 = ph1[2 * ks], aH2 = ph0[2 * ks + 1], aH3 = ph1[2 * ks + 1];
            uint32_t aL0 = pl0[2 * ks], aL1 = pl1[2 * ks], aL2 = pl0[2 * ks + 1], aL3 = pl1[2 * ks + 1];
#pragma unroll
            for (int nt = 0; nt < 8; ++nt) {
                const __nv_bfloat16* bph = Vh[cur] + (nt * 8 + g) * PAD + ks * 16;
                const __nv_bfloat16* bpl = Vl[cur] + (nt * 8 + g) * PAD + ks * 16;
                uint32_t bH0 = ld32(bph + 2 * tq), bH1 = ld32(bph + 2 * tq + 8);
                uint32_t bL0 = ld32(bpl + 2 * tq), bL1 = ld32(bpl + 2 * tq + 8);
                mma_bf16(d[nt], aH0, aH1, aH2, aH3, bH0, bH1);
                mma_bf16(d[nt], aH0, aH1, aH2, aH3, bL0, bL1);
                mma_bf16(d[nt], aL0, aL1, aL2, aL3, bH0, bH1);
            }
        }

        // ---- STS prefetched next chunk into alternate buffer ----
        if (kc + 1 < 32) {
            const int nb = cur ^ 1;
            *(uint4*)(Kh[nb] + sr0 * PAD + sc0) = pf[0];
            *(uint4*)(Kh[nb] + sr1 * PAD + sc1) = pf[1];
            *(uint4*)(Kl[nb] + sr0 * PAD + sc0) = pf[2];
            *(uint4*)(Kl[nb] + sr1 * PAD + sc1) = pf[3];
            *(uint4*)(Vh[nb] + sr0 * PAD + sc0) = pf[4];
            *(uint4*)(Vh[nb] + sr1 * PAD + sc1) = pf[5];
            *(uint4*)(Vl[nb] + sr0 * PAD + sc0) = pf[6];
            *(uint4*)(Vl[nb] + sr1 * PAD + sc1) = pf[7];
        }
    }

    // ---- final: row sums -> g_inv, context = acc * inv ----
    rs0 += __shfl_xor_sync(0xffffffffu, rs0, 1);
    rs0 += __shfl_xor_sync(0xffffffffu, rs0, 2);
    rs1 += __shfl_xor_sync(0xffffffffu, rs1, 1);
    rs1 += __shfl_xor_sync(0xffffffffu, rs1, 2);
    const float inv0 = 1.0f / rs0, inv1 = 1.0f / rs1;
    if (tq == 0) {
        g_inv[(size_t)bh * S_LEN + q0 + m0 + g]     = inv0;
        g_inv[(size_t)bh * S_LEN + q0 + m0 + g + 8] = inv1;
    }
    float* Cb = C + ((size_t)bh * S_LEN + q0) * DK;
#pragma unroll
    for (int nt = 0; nt < 8; ++nt) {
        const int dc = nt * 8 + 2 * tq;
        *(float2*)(Cb + (size_t)(m0 + g) * DK + dc) =
            make_float2(d[nt][0] * inv0, d[nt][1] * inv0);
        *(float2*)(Cb + (size_t)(m0 + g + 8) * DK + dc) =
            make_float2(d[nt][2] * inv1, d[nt][3] * inv1);
    }
}

// =======================================================================================
// Normalize E in place: E[row][*] *= g_inv[row]. Pure stream.
// =======================================================================================
__global__ __launch_bounds__(256)
void norm_E(float* __restrict__ E)
{
    const size_t gidx = (size_t)blockIdx.x * 256 + threadIdx.x;   // float4 index
    const int row = (int)(gidx >> 9);                              // 512 float4 per row
    const float inv = g_inv[row];
    float4 v = *(const float4*)(E + gidx * 4);
    v.x *= inv; v.y *= inv; v.z *= inv; v.w *= inv;
    *(float4*)(E + gidx * 4) = v;
}

// =======================================================================================
extern "C" void kernel_launch(void* const* d_in, const int* in_sizes, int n_in,
                              void* d_out, int out_size)
{
    const float* Q = (const float*)d_in[0];
    const float* K = (const float*)d_in[1];
    const float* V = (const float*)d_in[2];
    const int*   M = (const int*)d_in[3];

    float* ctx = (float*)d_out;
    float* E   = ctx + (size_t)BH_N * S_LEN * DK;

    const int smem_f = 110592;
    cudaFuncSetAttribute(attn_fused, cudaFuncAttributeMaxDynamicSharedMemorySize, smem_f);

    convert_qk<<<dim3(4096, 2), 256>>>(Q, K);
    convert_v<<<dim3(32, BH_N), 256>>>(V);
    attn_fused<<<dim3(16, BH_N), 256, smem_f>>>(M, E, ctx);
    norm_E<<<(int)(((size_t)BH_N * S_LEN * S_LEN / 4) / 256), 256>>>(E);
}

// round 8
// speedup vs baseline: 1.7698x; 1.0910x over previous
#include <cuda_runtime.h>
#include <cuda_bf16.h>
#include <cstdint>

#define S_LEN 2048
#define DK 64
#define BH_N 32
#define SCALE 0.125f
#define PAD 72   // padded smem row stride (elems): fragment LDS conflict-free

// ---------------- static device scratch (no allocations allowed) ----------------
__device__ float g_inv[BH_N * S_LEN];
__device__ uint2 g_mbits[BH_N * S_LEN * 32];          // 2-bit-per-col mask words
__device__ __nv_bfloat16 g_Qhi[BH_N * S_LEN * DK];
__device__ __nv_bfloat16 g_Qlo[BH_N * S_LEN * DK];
__device__ __nv_bfloat16 g_Khi[BH_N * S_LEN * DK];
__device__ __nv_bfloat16 g_Klo[BH_N * S_LEN * DK];
__device__ __nv_bfloat16 g_Vthi[BH_N * DK * S_LEN];   // [bh][d][s]
__device__ __nv_bfloat16 g_Vtlo[BH_N * DK * S_LEN];

// ---------------- helpers ----------------
__device__ __forceinline__ unsigned short bf_us(__nv_bfloat16 h) {
    return __bfloat16_as_ushort(h);
}
__device__ __forceinline__ void split2(float x, float y, uint32_t& hi, uint32_t& lo) {
    __nv_bfloat16 hx = __float2bfloat16(x), hy = __float2bfloat16(y);
    __nv_bfloat16 lx = __float2bfloat16(x - __bfloat162float(hx));
    __nv_bfloat16 ly = __float2bfloat16(y - __bfloat162float(hy));
    hi = (uint32_t)bf_us(hx) | ((uint32_t)bf_us(hy) << 16);
    lo = (uint32_t)bf_us(lx) | ((uint32_t)bf_us(ly) << 16);
}
__device__ __forceinline__ uint32_t ld32(const __nv_bfloat16* p) {
    return *(const uint32_t*)p;
}
__device__ __forceinline__ void mma_bf16(float* c, uint32_t a0, uint32_t a1,
                                         uint32_t a2, uint32_t a3,
                                         uint32_t b0, uint32_t b1) {
    asm volatile(
        "mma.sync.aligned.m16n8k16.row.col.f32.bf16.bf16.f32 "
        "{%0,%1,%2,%3}, {%4,%5,%6,%7}, {%8,%9}, {%0,%1,%2,%3};"
        : "+f"(c[0]), "+f"(c[1]), "+f"(c[2]), "+f"(c[3])
        : "r"(a0), "r"(a1), "r"(a2), "r"(a3), "r"(b0), "r"(b1));
}
// cp.async 16B (LDGSTS; baseline PTX, sm_80+)
__device__ __forceinline__ void cp16(void* s, const void* g) {
    uint32_t sa = (uint32_t)__cvta_generic_to_shared(s);
    asm volatile("cp.async.cg.shared.global [%0], [%1], 16;" :: "r"(sa), "l"(g));
}
#define CP_COMMIT() asm volatile("cp.async.commit_group;" ::: "memory")
#define CP_WAIT(n)  asm volatile("cp.async.wait_group %0;" :: "n"(n) : "memory")

// =======================================================================================
// K0a: Q,K fp32 -> bf16 hi/lo
// =======================================================================================
__global__ __launch_bounds__(256)
void convert_qk(const float* __restrict__ Q, const float* __restrict__ K)
{
    const size_t i = ((size_t)blockIdx.x * 256 + threadIdx.x) * 4;
    const float* src = blockIdx.y ? K : Q;
    __nv_bfloat16* hi = blockIdx.y ? g_Khi : g_Qhi;
    __nv_bfloat16* lo = blockIdx.y ? g_Klo : g_Qlo;
    float4 v = *(const float4*)(src + i);
    uint2 h, l;
    split2(v.x, v.y, h.x, l.x);
    split2(v.z, v.w, h.y, l.y);
    *(uint2*)(hi + i) = h;
    *(uint2*)(lo + i) = l;
}

// =======================================================================================
// K0b: V [bh][s][d] fp32 -> transposed Vt [bh][d][s] bf16 hi/lo
// =======================================================================================
__global__ __launch_bounds__(256)
void convert_v(const float* __restrict__ V)
{
    __shared__ float sm[64 * 65];
    const int bh = blockIdx.y;
    const int k0 = blockIdx.x * 64;
    const float* Vb = V + ((size_t)bh * S_LEN + k0) * DK;
    const int t = threadIdx.x;
#pragma unroll
    for (int i = 0; i < 4; ++i) {
        int idx = i * 256 + t;
        int row = idx >> 4, c4 = (idx & 15) * 4;
        float4 v = *(const float4*)(Vb + (size_t)row * DK + c4);
        sm[row * 65 + c4 + 0] = v.x; sm[row * 65 + c4 + 1] = v.y;
        sm[row * 65 + c4 + 2] = v.z; sm[row * 65 + c4 + 3] = v.w;
    }
    __syncthreads();
    const int d = t >> 2, qtr = t & 3;
    __nv_bfloat16* ph = g_Vthi + ((size_t)bh * DK + d) * S_LEN + k0 + qtr * 16;
    __nv_bfloat16* pl = g_Vtlo + ((size_t)bh * DK + d) * S_LEN + k0 + qtr * 16;
    uint32_t hw[8], lw[8];
#pragma unroll
    for (int j = 0; j < 8; ++j) {
        float a = sm[(qtr * 16 + 2 * j + 0) * 65 + d];
        float b = sm[(qtr * 16 + 2 * j + 1) * 65 + d];
        split2(a, b, hw[j], lw[j]);
    }
    *(uint4*)(ph + 0) = make_uint4(hw[0], hw[1], hw[2], hw[3]);
    *(uint4*)(ph + 8) = make_uint4(hw[4], hw[5], hw[6], hw[7]);
    *(uint4*)(pl + 0) = make_uint4(lw[0], lw[1], lw[2], lw[3]);
    *(uint4*)(pl + 8) = make_uint4(lw[4], lw[5], lw[6], lw[7]);
}

// =======================================================================================
// K0c: compact int32 mask -> 2 ballot words per (row, 64-col chunk).
// bit p of .x = col 2p masked; bit p of .y = col 2p+1 masked.
// =======================================================================================
__global__ __launch_bounds__(256)
void mask_compact(const int* __restrict__ M)
{
    const int w = blockIdx.x * 8 + (threadIdx.x >> 5);
    const int lane = threadIdx.x & 31;
    const int chunk = w & 31;
    const int row = w >> 5;                      // 0 .. BH_N*S_LEN-1
    int2 m = *(const int2*)(M + (size_t)row * S_LEN + chunk * 64 + lane * 2);
    uint32_t be = __ballot_sync(0xffffffffu, m.x != 0);
    uint32_t bo = __ballot_sync(0xffffffffu, m.y != 0);
    if (lane == 0) g_mbits[(size_t)row * 32 + chunk] = make_uint2(be, bo);
}

// =======================================================================================
// Fused attention. 8 warps, warp tile 16(m) x 64(n), 32 k-chunks of 64.
// cp.async double-buffered K/V staging; bitmask epilogue; P packed in registers for PV.
// smem: Qh@0 Ql@18432 (128xPAD), Kh2@36864, Kl2@55296, Vh2@73728, Vl2@92160. 110592B.
// =======================================================================================
__global__ __launch_bounds__(256, 2)
void attn_fused(float* __restrict__ E, float* __restrict__ C)
{
    extern __shared__ char smem[];
    __nv_bfloat16* Qh = (__nv_bfloat16*)(smem);
    __nv_bfloat16* Ql = (__nv_bfloat16*)(smem + 18432);
    __nv_bfloat16* Kh[2] = { (__nv_bfloat16*)(smem + 36864), (__nv_bfloat16*)(smem + 46080) };
    __nv_bfloat16* Kl[2] = { (__nv_bfloat16*)(smem + 55296), (__nv_bfloat16*)(smem + 64512) };
    __nv_bfloat16* Vh[2] = { (__nv_bfloat16*)(smem + 73728), (__nv_bfloat16*)(smem + 82944) };
    __nv_bfloat16* Vl[2] = { (__nv_bfloat16*)(smem + 92160), (__nv_bfloat16*)(smem + 101376) };

    const int t = threadIdx.x, wid = t >> 5, lane = t & 31;
    const int g = lane >> 2, tq = lane & 3;
    const int bh = blockIdx.y, q0 = blockIdx.x * 128;
    const int m0 = wid * 16;

    const __nv_bfloat16* Kp_h = g_Khi + ((size_t)bh * S_LEN) * DK;
    const __nv_bfloat16* Kp_l = g_Klo + ((size_t)bh * S_LEN) * DK;
    const __nv_bfloat16* Vp_h = g_Vthi + (size_t)bh * DK * S_LEN;
    const __nv_bfloat16* Vp_l = g_Vtlo + (size_t)bh * DK * S_LEN;

    const int sr0 = t >> 3, sc0 = (t & 7) * 8;
    const int sr1 = (t + 256) >> 3, sc1 = ((t + 256) & 7) * 8;

    // async-stage a 64-k chunk into buffer b
#define STAGE(kn, b) do {                                                                  \
        cp16(Kh[b] + sr0 * PAD + sc0, Kp_h + (size_t)((kn) + sr0) * DK + sc0);             \
        cp16(Kh[b] + sr1 * PAD + sc1, Kp_h + (size_t)((kn) + sr1) * DK + sc1);             \
        cp16(Kl[b] + sr0 * PAD + sc0, Kp_l + (size_t)((kn) + sr0) * DK + sc0);             \
        cp16(Kl[b] + sr1 * PAD + sc1, Kp_l + (size_t)((kn) + sr1) * DK + sc1);             \
        cp16(Vh[b] + sr0 * PAD + sc0, Vp_h + (size_t)sr0 * S_LEN + (kn) + sc0);            \
        cp16(Vh[b] + sr1 * PAD + sc1, Vp_h + (size_t)sr1 * S_LEN + (kn) + sc1);            \
        cp16(Vl[b] + sr0 * PAD + sc0, Vp_l + (size_t)sr0 * S_LEN + (kn) + sc0);            \
        cp16(Vl[b] + sr1 * PAD + sc1, Vp_l + (size_t)sr1 * S_LEN + (kn) + sc1);            \
    } while (0)

    STAGE(0, 0);
    CP_COMMIT();

    // stage Q (plain LDG/STS; covered by the kc=0 sync)
    {
        const __nv_bfloat16* qh = g_Qhi + ((size_t)bh * S_LEN + q0) * DK;
        const __nv_bfloat16* ql = g_Qlo + ((size_t)bh * S_LEN + q0) * DK;
#pragma unroll
        for (int i = 0; i < 4; ++i) {
            int idx = i * 256 + t;
            int r = idx >> 3, c8 = (idx & 7) * 8;
            *(uint4*)(Qh + r * PAD + c8) = *(const uint4*)(qh + r * DK + c8);
            *(uint4*)(Ql + r * PAD + c8) = *(const uint4*)(ql + r * DK + c8);
        }
    }

    float d[8][4];
#pragma unroll
    for (int nt = 0; nt < 8; ++nt)
#pragma unroll
        for (int j = 0; j < 4; ++j) d[nt][j] = 0.f;
    float rs0 = 0.f, rs1 = 0.f;

    float* Eb = E + ((size_t)bh * S_LEN + q0) * S_LEN;
    const uint2* mb0 = g_mbits + ((size_t)bh * S_LEN + q0 + m0 + g) * 32;
    const uint2* mb1 = g_mbits + ((size_t)bh * S_LEN + q0 + m0 + g + 8) * 32;

    for (int kc = 0; kc < 32; ++kc) {
        const int cur = kc & 1;
        if (kc + 1 < 32) {
            STAGE((kc + 1) * 64, cur ^ 1);
            CP_COMMIT();
            CP_WAIT(1);
        } else {
            CP_WAIT(0);
        }
        __syncthreads();

        // mask words for this chunk (latency hidden under QK mma)
        uint2 w0 = mb0[kc], w1 = mb1[kc];

        // ---- QK mma ----
        float c[8][4];
#pragma unroll
        for (int nt = 0; nt < 8; ++nt)
#pragma unroll
            for (int j = 0; j < 4; ++j) c[nt][j] = 0.f;

#pragma unroll
        for (int ks = 0; ks < 4; ++ks) {
            const __nv_bfloat16* aph = Qh + (m0 + g) * PAD + ks * 16;
            const __nv_bfloat16* apl = Ql + (m0 + g) * PAD + ks * 16;
            uint32_t aH[4] = { ld32(aph + 2 * tq), ld32(aph + 8 * PAD + 2 * tq),
                               ld32(aph + 2 * tq + 8), ld32(aph + 8 * PAD + 2 * tq + 8) };
            uint32_t aL[4] = { ld32(apl + 2 * tq), ld32(apl + 8 * PAD + 2 * tq),
                               ld32(apl + 2 * tq + 8), ld32(apl + 8 * PAD + 2 * tq + 8) };
#pragma unroll
            for (int nt = 0; nt < 8; ++nt) {
                const __nv_bfloat16* bph = Kh[cur] + (nt * 8 + g) * PAD + ks * 16;
                const __nv_bfloat16* bpl = Kl[cur] + (nt * 8 + g) * PAD + ks * 16;
                uint32_t bH0 = ld32(bph + 2 * tq), bH1 = ld32(bph + 2 * tq + 8);
                uint32_t bL0 = ld32(bpl + 2 * tq), bL1 = ld32(bpl + 2 * tq + 8);
                mma_bf16(c[nt], aH[0], aH[1], aH[2], aH[3], bH0, bH1);
                mma_bf16(c[nt], aH[0], aH[1], aH[2], aH[3], bL0, bL1);
                mma_bf16(c[nt], aL[0], aL[1], aL[2], aL[3], bH0, bH1);
            }
        }

        // ---- epilogue: exp + bitmask + E store + row sums + pack P ----
        uint32_t ph0[8], ph1[8], pl0[8], pl1[8];
#pragma unroll
        for (int nt = 0; nt < 8; ++nt) {
            const int pos = nt * 4 + tq;
            float e0 = ((w0.x >> pos) & 1u) ? 0.f : __expf(c[nt][0] * SCALE);
            float e1 = ((w0.y >> pos) & 1u) ? 0.f : __expf(c[nt][1] * SCALE);
            float e2 = ((w1.x >> pos) & 1u) ? 0.f : __expf(c[nt][2] * SCALE);
            float e3 = ((w1.y >> pos) & 1u) ? 0.f : __expf(c[nt][3] * SCALE);
            const size_t col = (size_t)kc * 64 + nt * 8 + 2 * tq;
            *(float2*)(Eb + (size_t)(m0 + g) * S_LEN + col)     = make_float2(e0, e1);
            *(float2*)(Eb + (size_t)(m0 + g + 8) * S_LEN + col) = make_float2(e2, e3);
            rs0 += e0 + e1;
            rs1 += e2 + e3;
            split2(e0, e1, ph0[nt], pl0[nt]);
            split2(e2, e3, ph1[nt], pl1[nt]);
        }

        // ---- PV mma: A = packed P (regs), B = Vt chunk (smem) ----
#pragma unroll
        for (int ks = 0; ks < 4; ++ks) {
            uint32_t aH0 = ph0[2 * ks], aH1 = ph1[2 * ks], aH2 = ph0[2 * ks + 1], aH3 = ph1[2 * ks + 1];
            uint32_t aL0 = pl0[2 * ks], aL1 = pl1[2 * ks], aL2 = pl0[2 * ks + 1], aL3 = pl1[2 * ks + 1];
#pragma unroll
            for (int nt = 0; nt < 8; ++nt) {
                const __nv_bfloat16* bph = Vh[cur] + (nt * 8 + g) * PAD + ks * 16;
                const __nv_bfloat16* bpl = Vl[cur] + (nt * 8 + g) * PAD + ks * 16;
                uint32_t bH0 = ld32(bph + 2 * tq), bH1 = ld32(bph + 2 * tq + 8);
                uint32_t bL0 = ld32(bpl + 2 * tq), bL1 = ld32(bpl + 2 * tq + 8);
                mma_bf16(d[nt], aH0, aH1, aH2, aH3, bH0, bH1);
                mma_bf16(d[nt], aH0, aH1, aH2, aH3, bL0, bL1);
                mma_bf16(d[nt], aL0, aL1, aL2, aL3, bH0, bH1);
            }
        }
        __syncthreads();
    }

    // ---- final: row sums -> g_inv, context = acc * inv ----
    rs0 += __shfl_xor_sync(0xffffffffu, rs0, 1);
    rs0 += __shfl_xor_sync(0xffffffffu, rs0, 2);
    rs1 += __shfl_xor_sync(0xffffffffu, rs1, 1);
    rs1 += __shfl_xor_sync(0xffffffffu, rs1, 2);
    const float inv0 = 1.0f / rs0, inv1 = 1.0f / rs1;
    if (tq == 0) {
        g_inv[(size_t)bh * S_LEN + q0 + m0 + g]     = inv0;
        g_inv[(size_t)bh * S_LEN + q0 + m0 + g + 8] = inv1;
    }
    float* Cb = C + ((size_t)bh * S_LEN + q0) * DK;
#pragma unroll
    for (int nt = 0; nt < 8; ++nt) {
        const int dc = nt * 8 + 2 * tq;
        *(float2*)(Cb + (size_t)(m0 + g) * DK + dc) =
            make_float2(d[nt][0] * inv0, d[nt][1] * inv0);
        *(float2*)(Cb + (size_t)(m0 + g + 8) * DK + dc) =
            make_float2(d[nt][2] * inv1, d[nt][3] * inv1);
    }
#undef STAGE
}

// =======================================================================================
// Normalize E in place: E[row][*] *= g_inv[row]. Pure stream.
// =======================================================================================
__global__ __launch_bounds__(256)
void norm_E(float* __restrict__ E)
{
    const size_t gidx = (size_t)blockIdx.x * 256 + threadIdx.x;   // float4 index
    const int row = (int)(gidx >> 9);                              // 512 float4 per row
    const float inv = g_inv[row];
    float4 v = *(const float4*)(E + gidx * 4);
    v.x *= inv; v.y *= inv; v.z *= inv; v.w *= inv;
    *(float4*)(E + gidx * 4) = v;
}

// =======================================================================================
extern "C" void kernel_launch(void* const* d_in, const int* in_sizes, int n_in,
                              void* d_out, int out_size)
{
    const float* Q = (const float*)d_in[0];
    const float* K = (const float*)d_in[1];
    const float* V = (const float*)d_in[2];
    const int*   M = (const int*)d_in[3];

    float* ctx = (float*)d_out;
    float* E   = ctx + (size_t)BH_N * S_LEN * DK;

    const int smem_f = 110592;
    cudaFuncSetAttribute(attn_fused, cudaFuncAttributeMaxDynamicSharedMemorySize, smem_f);

    convert_qk<<<dim3(4096, 2), 256>>>(Q, K);
    convert_v<<<dim3(32, BH_N), 256>>>(V);
    mask_compact<<<(BH_N * S_LEN * 32) / 8, 256>>>(M);
    attn_fused<<<dim3(16, BH_N), 256, smem_f>>>(E, ctx);
    norm_E<<<(int)(((size_t)BH_N * S_LEN * S_LEN / 4) / 256), 256>>>(E);
}

// round 11
// speedup vs baseline: 1.9763x; 1.1167x over previous
#include <cuda_runtime.h>
#include <cuda_bf16.h>
#include <cstdint>

#define S_LEN 2048
#define DK 64
#define BH_N 32
#define SCALE 0.125f
#define PAD 72   // padded smem row stride (elems): 144B rows -> conflict-free ldmatrix

// ---------------- static device scratch (no allocations allowed) ----------------
__device__ float g_inv[BH_N * S_LEN];
__device__ uint2 g_mbits[BH_N * S_LEN * 32];          // 2-bit-per-col mask words
__device__ __nv_bfloat16 g_Qhi[BH_N * S_LEN * DK];
__device__ __nv_bfloat16 g_Qlo[BH_N * S_LEN * DK];
__device__ __nv_bfloat16 g_Khi[BH_N * S_LEN * DK];
__device__ __nv_bfloat16 g_Klo[BH_N * S_LEN * DK];
__device__ __nv_bfloat16 g_Vthi[BH_N * DK * S_LEN];   // [bh][d][s]
__device__ __nv_bfloat16 g_Vtlo[BH_N * DK * S_LEN];

// ---------------- helpers ----------------
__device__ __forceinline__ unsigned short bf_us(__nv_bfloat16 h) {
    return __bfloat16_as_ushort(h);
}
__device__ __forceinline__ void split2(float x, float y, uint32_t& hi, uint32_t& lo) {
    __nv_bfloat16 hx = __float2bfloat16(x), hy = __float2bfloat16(y);
    __nv_bfloat16 lx = __float2bfloat16(x - __bfloat162float(hx));
    __nv_bfloat16 ly = __float2bfloat16(y - __bfloat162float(hy));
    hi = (uint32_t)bf_us(hx) | ((uint32_t)bf_us(hy) << 16);
    lo = (uint32_t)bf_us(lx) | ((uint32_t)bf_us(ly) << 16);
}
__device__ __forceinline__ void mma_bf16(float* c, uint32_t a0, uint32_t a1,
                                         uint32_t a2, uint32_t a3,
                                         uint32_t b0, uint32_t b1) {
    asm volatile(
        "mma.sync.aligned.m16n8k16.row.col.f32.bf16.bf16.f32 "
        "{%0,%1,%2,%3}, {%4,%5,%6,%7}, {%8,%9}, {%0,%1,%2,%3};"
        : "+f"(c[0]), "+f"(c[1]), "+f"(c[2]), "+f"(c[3])
        : "r"(a0), "r"(a1), "r"(a2), "r"(a3), "r"(b0), "r"(b1));
}
// ldmatrix x4 (sm_75+ baseline)
__device__ __forceinline__ void lm4(uint32_t* r, uint32_t saddr) {
    asm volatile("ldmatrix.sync.aligned.m8n8.x4.shared.b16 {%0,%1,%2,%3}, [%4];"
                 : "=r"(r[0]), "=r"(r[1]), "=r"(r[2]), "=r"(r[3]) : "r"(saddr));
}
// cp.async 16B (LDGSTS; baseline PTX, sm_80+)
__device__ __forceinline__ void cp16(void* s, const void* g) {
    uint32_t sa = (uint32_t)__cvta_generic_to_shared(s);
    asm volatile("cp.async.cg.shared.global [%0], [%1], 16;" :: "r"(sa), "l"(g));
}
#define CP_COMMIT() asm volatile("cp.async.commit_group;" ::: "memory")
#define CP_WAIT(n)  asm volatile("cp.async.wait_group %0;" :: "n"(n) : "memory")

// =======================================================================================
// K0a: Q,K fp32 -> bf16 hi/lo
// =======================================================================================
__global__ __launch_bounds__(256)
void convert_qk(const float* __restrict__ Q, const float* __restrict__ K)
{
    const size_t i = ((size_t)blockIdx.x * 256 + threadIdx.x) * 4;
    const float* src = blockIdx.y ? K : Q;
    __nv_bfloat16* hi = blockIdx.y ? g_Khi : g_Qhi;
    __nv_bfloat16* lo = blockIdx.y ? g_Klo : g_Qlo;
    float4 v = *(const float4*)(src + i);
    uint2 h, l;
    split2(v.x, v.y, h.x, l.x);
    split2(v.z, v.w, h.y, l.y);
    *(uint2*)(hi + i) = h;
    *(uint2*)(lo + i) = l;
}

// =======================================================================================
// K0b: V [bh][s][d] fp32 -> transposed Vt [bh][d][s] bf16 hi/lo
// =======================================================================================
__global__ __launch_bounds__(256)
void convert_v(const float* __restrict__ V)
{
    __shared__ float sm[64 * 65];
    const int bh = blockIdx.y;
    const int k0 = blockIdx.x * 64;
    const float* Vb = V + ((size_t)bh * S_LEN + k0) * DK;
    const int t = threadIdx.x;
#pragma unroll
    for (int i = 0; i < 4; ++i) {
        int idx = i * 256 + t;
        int row = idx >> 4, c4 = (idx & 15) * 4;
        float4 v = *(const float4*)(Vb + (size_t)row * DK + c4);
        sm[row * 65 + c4 + 0] = v.x; sm[row * 65 + c4 + 1] = v.y;
        sm[row * 65 + c4 + 2] = v.z; sm[row * 65 + c4 + 3] = v.w;
    }
    __syncthreads();
    const int d = t >> 2, qtr = t & 3;
    __nv_bfloat16* ph = g_Vthi + ((size_t)bh * DK + d) * S_LEN + k0 + qtr * 16;
    __nv_bfloat16* pl = g_Vtlo + ((size_t)bh * DK + d) * S_LEN + k0 + qtr * 16;
    uint32_t hw[8], lw[8];
#pragma unroll
    for (int j = 0; j < 8; ++j) {
        float a = sm[(qtr * 16 + 2 * j + 0) * 65 + d];
        float b = sm[(qtr * 16 + 2 * j + 1) * 65 + d];
        split2(a, b, hw[j], lw[j]);
    }
    *(uint4*)(ph + 0) = make_uint4(hw[0], hw[1], hw[2], hw[3]);
    *(uint4*)(ph + 8) = make_uint4(hw[4], hw[5], hw[6], hw[7]);
    *(uint4*)(pl + 0) = make_uint4(lw[0], lw[1], lw[2], lw[3]);
    *(uint4*)(pl + 8) = make_uint4(lw[4], lw[5], lw[6], lw[7]);
}

// =======================================================================================
// K0c: compact int32 mask -> 2 ballot words per (row, 64-col chunk).
// =======================================================================================
__global__ __launch_bounds__(256)
void mask_compact(const int* __restrict__ M)
{
    const int w = blockIdx.x * 8 + (threadIdx.x >> 5);
    const int lane = threadIdx.x & 31;
    const int chunk = w & 31;
    const int row = w >> 5;
    int2 m = *(const int2*)(M + (size_t)row * S_LEN + chunk * 64 + lane * 2);
    uint32_t be = __ballot_sync(0xffffffffu, m.x != 0);
    uint32_t bo = __ballot_sync(0xffffffffu, m.y != 0);
    if (lane == 0) g_mbits[(size_t)row * 32 + chunk] = make_uint2(be, bo);
}

// =======================================================================================
// Fused attention. 8 warps, warp tile 16(m) x 64(n), 32 k-chunks of 64.
// ldmatrix.x4 fragment loads; cp.async double-buffered K/V staging; bitmask epilogue;
// P packed in registers for PV.
// smem: Qh@0 Ql@18432 (128xPAD), Kh2@36864, Kl2@55296, Vh2@73728, Vl2@92160. 110592B.
// =======================================================================================
__global__ __launch_bounds__(256, 2)
void attn_fused(float* __restrict__ E, float* __restrict__ C)
{
    extern __shared__ char smem[];
    __nv_bfloat16* Qh = (__nv_bfloat16*)(smem);
    __nv_bfloat16* Ql = (__nv_bfloat16*)(smem + 18432);
    __nv_bfloat16* Kh[2] = { (__nv_bfloat16*)(smem + 36864), (__nv_bfloat16*)(smem + 46080) };
    __nv_bfloat16* Kl[2] = { (__nv_bfloat16*)(smem + 55296), (__nv_bfloat16*)(smem + 64512) };
    __nv_bfloat16* Vh[2] = { (__nv_bfloat16*)(smem + 73728), (__nv_bfloat16*)(smem + 82944) };
    __nv_bfloat16* Vl[2] = { (__nv_bfloat16*)(smem + 92160), (__nv_bfloat16*)(smem + 101376) };

    const int t = threadIdx.x, wid = t >> 5, lane = t & 31;
    const int g = lane >> 2, tq = lane & 3;
    const int bh = blockIdx.y, q0 = blockIdx.x * 128;
    const int m0 = wid * 16;

    const __nv_bfloat16* Kp_h = g_Khi + ((size_t)bh * S_LEN) * DK;
    const __nv_bfloat16* Kp_l = g_Klo + ((size_t)bh * S_LEN) * DK;
    const __nv_bfloat16* Vp_h = g_Vthi + (size_t)bh * DK * S_LEN;
    const __nv_bfloat16* Vp_l = g_Vtlo + (size_t)bh * DK * S_LEN;

    const int sr0 = t >> 3, sc0 = (t & 7) * 8;
    const int sr1 = (t + 256) >> 3, sc1 = ((t + 256) & 7) * 8;

#define STAGE(kn, b) do {                                                                  \
        cp16(Kh[b] + sr0 * PAD + sc0, Kp_h + (size_t)((kn) + sr0) * DK + sc0);             \
        cp16(Kh[b] + sr1 * PAD + sc1, Kp_h + (size_t)((kn) + sr1) * DK + sc1);             \
        cp16(Kl[b] + sr0 * PAD + sc0, Kp_l + (size_t)((kn) + sr0) * DK + sc0);             \
        cp16(Kl[b] + sr1 * PAD + sc1, Kp_l + (size_t)((kn) + sr1) * DK + sc1);             \
        cp16(Vh[b] + sr0 * PAD + sc0, Vp_h + (size_t)sr0 * S_LEN + (kn) + sc0);            \
        cp16(Vh[b] + sr1 * PAD + sc1, Vp_h + (size_t)sr1 * S_LEN + (kn) + sc1);            \
        cp16(Vl[b] + sr0 * PAD + sc0, Vp_l + (size_t)sr0 * S_LEN + (kn) + sc0);            \
        cp16(Vl[b] + sr1 * PAD + sc1, Vp_l + (size_t)sr1 * S_LEN + (kn) + sc1);            \
    } while (0)

    STAGE(0, 0);
    CP_COMMIT();

    // stage Q (plain LDG/STS; covered by the kc=0 sync)
    {
        const __nv_bfloat16* qh = g_Qhi + ((size_t)bh * S_LEN + q0) * DK;
        const __nv_bfloat16* ql = g_Qlo + ((size_t)bh * S_LEN + q0) * DK;
#pragma unroll
        for (int i = 0; i < 4; ++i) {
            int idx = i * 256 + t;
            int r = idx >> 3, c8 = (idx & 7) * 8;
            *(uint4*)(Qh + r * PAD + c8) = *(const uint4*)(qh + r * DK + c8);
            *(uint4*)(Ql + r * PAD + c8) = *(const uint4*)(ql + r * DK + c8);
        }
    }

    // ---- per-lane ldmatrix addresses (bytes, shared space) ----
    // A quadrants: rows [m, m+8] x cols [k, k+8]
    const int a_row = m0 + (lane & 7) + ((lane >> 3) & 1) * 8;
    const int a_c8 = ((lane >> 4) & 1) * 8;
    const uint32_t aoff = (uint32_t)(a_row * PAD + a_c8) * 2;
    const uint32_t aQh = (uint32_t)__cvta_generic_to_shared(Qh) + aoff;
    const uint32_t aQl = (uint32_t)__cvta_generic_to_shared(Ql) + aoff;
    // B pairs: matrices {b0(nt), b1(nt), b0(nt+1), b1(nt+1)}
    const int b_rowoff = (lane & 7) + ((lane >> 4) & 1) * 8;
    const int b_c8 = ((lane >> 3) & 1) * 8;
    const uint32_t boff = (uint32_t)(b_rowoff * PAD + b_c8) * 2;
    const uint32_t sKh[2] = { (uint32_t)__cvta_generic_to_shared(Kh[0]) + boff,
                              (uint32_t)__cvta_generic_to_shared(Kh[1]) + boff };
    const uint32_t sKl[2] = { (uint32_t)__cvta_generic_to_shared(Kl[0]) + boff,
                              (uint32_t)__cvta_generic_to_shared(Kl[1]) + boff };
    const uint32_t sVh[2] = { (uint32_t)__cvta_generic_to_shared(Vh[0]) + boff,
                              (uint32_t)__cvta_generic_to_shared(Vh[1]) + boff };
    const uint32_t sVl[2] = { (uint32_t)__cvta_generic_to_shared(Vl[0]) + boff,
                              (uint32_t)__cvta_generic_to_shared(Vl[1]) + boff };
    // nt-pair stride = 16 rows * PAD * 2B; k-step stride = 16 elems * 2B
#define BSTEP(ntp, ks) ((uint32_t)(ntp) * (16 * PAD * 2) + (uint32_t)(ks) * 32)

    float d[8][4];
#pragma unroll
    for (int nt = 0; nt < 8; ++nt)
#pragma unroll
        for (int j = 0; j < 4; ++j) d[nt][j] = 0.f;
    float rs0 = 0.f, rs1 = 0.f;

    float* Eb = E + ((size_t)bh * S_LEN + q0) * S_LEN;
    const uint2* mb0 = g_mbits + ((size_t)bh * S_LEN + q0 + m0 + g) * 32;
    const uint2* mb1 = g_mbits + ((size_t)bh * S_LEN + q0 + m0 + g + 8) * 32;

    for (int kc = 0; kc < 32; ++kc) {
        const int cur = kc & 1;
        if (kc + 1 < 32) {
            STAGE((kc + 1) * 64, cur ^ 1);
            CP_COMMIT();
            CP_WAIT(1);
        } else {
            CP_WAIT(0);
        }
        __syncthreads();

        uint2 w0 = mb0[kc], w1 = mb1[kc];

        // ---- QK mma ----
        float c[8][4];
#pragma unroll
        for (int nt = 0; nt < 8; ++nt)
#pragma unroll
            for (int j = 0; j < 4; ++j) c[nt][j] = 0.f;

#pragma unroll
        for (int ks = 0; ks < 4; ++ks) {
            uint32_t aH[4], aL[4];
            lm4(aH, aQh + ks * 32);
            lm4(aL, aQl + ks * 32);
#pragma unroll
            for (int ntp = 0; ntp < 4; ++ntp) {
                uint32_t bH[4], bL[4];
                lm4(bH, sKh[cur] + BSTEP(ntp, ks));
                lm4(bL, sKl[cur] + BSTEP(ntp, ks));
                mma_bf16(c[2 * ntp],     aH[0], aH[1], aH[2], aH[3], bH[0], bH[1]);
                mma_bf16(c[2 * ntp],     aH[0], aH[1], aH[2], aH[3], bL[0], bL[1]);
                mma_bf16(c[2 * ntp],     aL[0], aL[1], aL[2], aL[3], bH[0], bH[1]);
                mma_bf16(c[2 * ntp + 1], aH[0], aH[1], aH[2], aH[3], bH[2], bH[3]);
                mma_bf16(c[2 * ntp + 1], aH[0], aH[1], aH[2], aH[3], bL[2], bL[3]);
                mma_bf16(c[2 * ntp + 1], aL[0], aL[1], aL[2], aL[3], bH[2], bH[3]);
            }
        }

        // ---- epilogue: exp + bitmask + E store + row sums + pack P ----
        uint32_t ph0[8], ph1[8], pl0[8], pl1[8];
#pragma unroll
        for (int nt = 0; nt < 8; ++nt) {
            const int pos = nt * 4 + tq;
            float e0 = ((w0.x >> pos) & 1u) ? 0.f : __expf(c[nt][0] * SCALE);
            float e1 = ((w0.y >> pos) & 1u) ? 0.f : __expf(c[nt][1] * SCALE);
            float e2 = ((w1.x >> pos) & 1u) ? 0.f : __expf(c[nt][2] * SCALE);
            float e3 = ((w1.y >> pos) & 1u) ? 0.f : __expf(c[nt][3] * SCALE);
            const size_t col = (size_t)kc * 64 + nt * 8 + 2 * tq;
            *(float2*)(Eb + (size_t)(m0 + g) * S_LEN + col)     = make_float2(e0, e1);
            *(float2*)(Eb + (size_t)(m0 + g + 8) * S_LEN + col) = make_float2(e2, e3);
            rs0 += e0 + e1;
            rs1 += e2 + e3;
            split2(e0, e1, ph0[nt], pl0[nt]);
            split2(e2, e3, ph1[nt], pl1[nt]);
        }

        // ---- PV mma: A = packed P (regs), B = Vt chunk (smem via ldmatrix) ----
#pragma unroll
        for (int ks = 0; ks < 4; ++ks) {
            uint32_t aH0 = ph0[2 * ks], aH1 = ph1[2 * ks], aH2 = ph0[2 * ks + 1], aH3 = ph1[2 * ks + 1];
            uint32_t aL0 = pl0[2 * ks], aL1 = pl1[2 * ks], aL2 = pl0[2 * ks + 1], aL3 = pl1[2 * ks + 1];
#pragma unroll
            for (int ntp = 0; ntp < 4; ++ntp) {
                uint32_t vH[4], vL[4];
                lm4(vH, sVh[cur] + BSTEP(ntp, ks));
                lm4(vL, sVl[cur] + BSTEP(ntp, ks));
                mma_bf16(d[2 * ntp],     aH0, aH1, aH2, aH3, vH[0], vH[1]);
                mma_bf16(d[2 * ntp],     aH0, aH1, aH2, aH3, vL[0], vL[1]);
                mma_bf16(d[2 * ntp],     aL0, aL1, aL2, aL3, vH[0], vH[1]);
                mma_bf16(d[2 * ntp + 1], aH0, aH1, aH2, aH3, vH[2], vH[3]);
                mma_bf16(d[2 * ntp + 1], aH0, aH1, aH2, aH3, vL[2], vL[3]);
                mma_bf16(d[2 * ntp + 1], aL0, aL1, aL2, aL3, vH[2], vH[3]);
            }
        }
        __syncthreads();
    }

    // ---- final: row sums -> g_inv, context = acc * inv ----
    rs0 += __shfl_xor_sync(0xffffffffu, rs0, 1);
    rs0 += __shfl_xor_sync(0xffffffffu, rs0, 2);
    rs1 += __shfl_xor_sync(0xffffffffu, rs1, 1);
    rs1 += __shfl_xor_sync(0xffffffffu, rs1, 2);
    const float inv0 = 1.0f / rs0, inv1 = 1.0f / rs1;
    if (tq == 0) {
        g_inv[(size_t)bh * S_LEN + q0 + m0 + g]     = inv0;
        g_inv[(size_t)bh * S_LEN + q0 + m0 + g + 8] = inv1;
    }
    float* Cb = C + ((size_t)bh * S_LEN + q0) * DK;
#pragma unroll
    for (int nt = 0; nt < 8; ++nt) {
        const int dc = nt * 8 + 2 * tq;
        *(float2*)(Cb + (size_t)(m0 + g) * DK + dc) =
            make_float2(d[nt][0] * inv0, d[nt][1] * inv0);
        *(float2*)(Cb + (size_t)(m0 + g + 8) * DK + dc) =
            make_float2(d[nt][2] * inv1, d[nt][3] * inv1);
    }
#undef STAGE
#undef BSTEP
}

// =======================================================================================
// Normalize E in place: E[row][*] *= g_inv[row]. Pure stream.
// =======================================================================================
__global__ __launch_bounds__(256)
void norm_E(float* __restrict__ E)
{
    const size_t gidx = (size_t)blockIdx.x * 256 + threadIdx.x;   // float4 index
    const int row = (int)(gidx >> 9);                              // 512 float4 per row
    const float inv = g_inv[row];
    float4 v = *(const float4*)(E + gidx * 4);
    v.x *= inv; v.y *= inv; v.z *= inv; v.w *= inv;
    *(float4*)(E + gidx * 4) = v;
}

// =======================================================================================
extern "C" void kernel_launch(void* const* d_in, const int* in_sizes, int n_in,
                              void* d_out, int out_size)
{
    const float* Q = (const float*)d_in[0];
    const float* K = (const float*)d_in[1];
    const float* V = (const float*)d_in[2];
    const int*   M = (const int*)d_in[3];

    float* ctx = (float*)d_out;
    float* E   = ctx + (size_t)BH_N * S_LEN * DK;

    const int smem_f = 110592;
    cudaFuncSetAttribute(attn_fused, cudaFuncAttributeMaxDynamicSharedMemorySize, smem_f);

    convert_qk<<<dim3(4096, 2), 256>>>(Q, K);
    convert_v<<<dim3(32, BH_N), 256>>>(V);
    mask_compact<<<(BH_N * S_LEN * 32) / 8, 256>>>(M);
    attn_fused<<<dim3(16, BH_N), 256, smem_f>>>(E, ctx);
    norm_E<<<(int)(((size_t)BH_N * S_LEN * S_LEN / 4) / 256), 256>>>(E);
}